// round 15
// baseline (speedup 1.0000x reference)
#include <cuda_runtime.h>
#include <cstdint>

namespace {

constexpr int KNN  = 32;   // K nearest neighbors
constexpr int IN2  = 64;   // 2K MLP input
constexpr int MID  = 32;   // hidden width of fc2
constexpr int HALF = 16;   // hidden units (columns) per lane; pair covers 32
constexpr int TPB  = 128;  // 4 warps/CTA -> one per SMSP

__device__ __forceinline__ float fast_tanh(float x) {
    float y;
    asm("tanh.approx.f32 %0, %1;" : "=f"(y) : "f"(x));
    return y;
}
__device__ __forceinline__ unsigned long long pack2(float x) {
    unsigned long long r;
    asm("mov.b64 %0, {%1, %1};" : "=l"(r) : "f"(x));
    return r;
}
__device__ __forceinline__ void ffma2(unsigned long long& d,
                                      unsigned long long a,
                                      unsigned long long b) {
    asm("fma.rn.f32x2 %0, %1, %2, %0;" : "+l"(d) : "l"(a), "l"(b));
}
__device__ __forceinline__ void unpack2(unsigned long long p, float& lo, float& hi) {
    asm("mov.b64 {%0, %1}, %2;" : "=f"(lo), "=f"(hi) : "l"(p));
}

// 2 CTAs/SM declared -> 255-reg budget; grid is only 128 CTAs anyway.
__global__ __launch_bounds__(TPB, 2) void meta_kernel(
    const int*   __restrict__ vals,
    const float* __restrict__ dist,
    const float* __restrict__ w1,   // [64,32]
    const float* __restrict__ b1,   // [32]
    const float* __restrict__ w2,   // [32,2]
    const float* __restrict__ b2,   // [2]
    const float* __restrict__ fw1,  // [2,4]
    const float* __restrict__ fb1,  // [4]
    const float* __restrict__ fw2,  // [4,1]
    const float* __restrict__ fb2,  // [1]
    float* __restrict__ out,        // [n,3]
    int n)
{
    __shared__ __align__(16) float s_w1[IN2 * MID];
    __shared__ __align__(16) float s_b1[MID];
    __shared__ __align__(16) float s_w2[MID * 2];

    {
        const int tid = threadIdx.x;
        #pragma unroll
        for (int i = 0; i < (IN2 * MID) / TPB; i++) s_w1[tid + i * TPB] = w1[tid + i * TPB];
        if (tid < MID)     s_b1[tid] = b1[tid];
        if (tid < MID * 2) s_w2[tid] = w2[tid];
        __syncthreads();
    }

    // lane pair handles 4 consecutive elements; each lane OWNS 2 of them
    // (even lane: base+0, base+1; odd lane: base+2, base+3) and 16 columns.
    const int gt   = blockIdx.x * TPB + threadIdx.x;
    const int half = gt & 1;
    const int base = (gt >> 1) * 4;
    if (base >= n) return;
    const int eA = base + 2 * half;        // my first owned element
    const int eB = eA + 1;                 // my second owned element
    const int off = half * HALF;

    // ---- issue all global loads up front (16 LDG.128 in flight) ----
    int4   vA[KNN / 4], vB[KNN / 4];
    float4 dA[KNN / 4], dB[KNN / 4];
    {
        const int4*   vpA = reinterpret_cast<const int4*>(vals + (size_t)eA * KNN);
        const int4*   vpB = reinterpret_cast<const int4*>(vals + (size_t)eB * KNN);
        const float4* dpA = reinterpret_cast<const float4*>(dist + (size_t)eA * KNN);
        const float4* dpB = reinterpret_cast<const float4*>(dist + (size_t)eB * KNN);
        #pragma unroll
        for (int c = 0; c < KNN / 4; c++) vA[c] = vpA[c];
        #pragma unroll
        for (int c = 0; c < KNN / 4; c++) vB[c] = vpB[c];
        #pragma unroll
        for (int c = 0; c < KNN / 4; c++) dA[c] = dpA[c];
        #pragma unroll
        for (int c = 0; c < KNN / 4; c++) dB[c] = dpB[c];
    }

    // ---- full-range 128-bit bitmaps for my 2 owned elements ----
    unsigned fA = 0u, fB = 0u;     // bit k = "first occurrence of nonzero label"
    {
        uint64_t loA = 1ull, hiA = 0ull, loB = 1ull, hiB = 0ull; // bit0: label 0 dead
        #pragma unroll
        for (int c = 0; c < KNN / 4; c++) {
            const int4 a = vA[c];
            const int4 b = vB[c];
            const int va[4] = {a.x, a.y, a.z, a.w};
            const int vb[4] = {b.x, b.y, b.z, b.w};
            #pragma unroll
            for (int r = 0; r < 4; r++) {
                const int k = 4 * c + r;
                {
                    const int val = va[r];
                    const uint64_t m = 1ull << (val & 63);
                    const bool hi = val >= 64;
                    const uint64_t w = hi ? hiA : loA;
                    if ((w & m) == 0ull) fA |= (1u << k);
                    if (hi) hiA |= m; else loA |= m;
                }
                {
                    const int val = vb[r];
                    const uint64_t m = 1ull << (val & 63);
                    const bool hi = val >= 64;
                    const uint64_t w = hi ? hiB : loB;
                    if ((w & m) == 0ull) fB |= (1u << k);
                    if (hi) hiB |= m; else loB |= m;
                }
            }
        }
    }
    // exchange flags with partner: index order [my0, my1, partner0, partner1]
    const unsigned fC = __shfl_xor_sync(0xffffffffu, fA, 1); // partner's first
    const unsigned fD = __shfl_xor_sync(0xffffffffu, fB, 1); // partner's second

    // ---- init packed accumulators: h[elem][8 x f32x2]; elem 0,1 = owned; 2,3 = partner's ----
    unsigned long long h[4][HALF / 2];
    {
        const ulonglong2* bp = reinterpret_cast<const ulonglong2*>(s_b1 + off);
        #pragma unroll
        for (int q = 0; q < HALF / 4; q++) {
            ulonglong2 t = bp[q];
            #pragma unroll
            for (int el = 0; el < 4; el++) {
                h[el][2*q+0] = t.x;
                h[el][2*q+1] = t.y;
            }
        }
    }

    // ---- phase B: label-count features; each weight load feeds 4 elements ----
    #pragma unroll
    for (int k = 0; k < KNN; k++) {
        const unsigned sh = 31 - k;
        const unsigned long long cc0 = pack2((float)__popc(fA << sh));
        const unsigned long long cc1 = pack2((float)__popc(fB << sh));
        const unsigned long long cc2 = pack2((float)__popc(fC << sh));
        const unsigned long long cc3 = pack2((float)__popc(fD << sh));
        const ulonglong2* wr = reinterpret_cast<const ulonglong2*>(
            s_w1 + (KNN + k) * MID + off);
        #pragma unroll
        for (int q = 0; q < HALF / 4; q++) {
            ulonglong2 w = wr[q];
            ffma2(h[0][2*q+0], cc0, w.x); ffma2(h[0][2*q+1], cc0, w.y);
            ffma2(h[1][2*q+0], cc1, w.x); ffma2(h[1][2*q+1], cc1, w.y);
            ffma2(h[2][2*q+0], cc2, w.x); ffma2(h[2][2*q+1], cc2, w.y);
            ffma2(h[3][2*q+0], cc3, w.x); ffma2(h[3][2*q+1], cc3, w.y);
        }
    }

    // ---- phase A: distance features; partner's x obtained via shfl per row ----
    #pragma unroll
    for (int c = 0; c < KNN / 4; c++) {
        const float4 ta = dA[c];
        const float4 tb = dB[c];
        const float xa[4] = {ta.x, ta.y, ta.z, ta.w};
        const float xb[4] = {tb.x, tb.y, tb.z, tb.w};
        #pragma unroll
        for (int r = 0; r < 4; r++) {
            const float x0 = xa[r];
            const float x1 = xb[r];
            const float x2 = __shfl_xor_sync(0xffffffffu, x0, 1); // partner's first
            const float x3 = __shfl_xor_sync(0xffffffffu, x1, 1); // partner's second
            const unsigned long long xx0 = pack2(x0);
            const unsigned long long xx1 = pack2(x1);
            const unsigned long long xx2 = pack2(x2);
            const unsigned long long xx3 = pack2(x3);
            const ulonglong2* wr = reinterpret_cast<const ulonglong2*>(
                s_w1 + (4 * c + r) * MID + off);
            #pragma unroll
            for (int q = 0; q < HALF / 4; q++) {
                ulonglong2 w = wr[q];
                ffma2(h[0][2*q+0], xx0, w.x); ffma2(h[0][2*q+1], xx0, w.y);
                ffma2(h[1][2*q+0], xx1, w.x); ffma2(h[1][2*q+1], xx1, w.y);
                ffma2(h[2][2*q+0], xx2, w.x); ffma2(h[2][2*q+1], xx2, w.y);
                ffma2(h[3][2*q+0], xx3, w.x); ffma2(h[3][2*q+1], xx3, w.y);
            }
        }
    }

    // ---- fc2 layer 2: partials over my 16 columns for all 4 elements ----
    float p0[4] = {0.f, 0.f, 0.f, 0.f};
    float p1[4] = {0.f, 0.f, 0.f, 0.f};
    #pragma unroll
    for (int q = 0; q < HALF / 2; q++) {
        const int j = 2 * q;
        const float wA0 = s_w2[2 * (off + j) + 0];
        const float wA1 = s_w2[2 * (off + j) + 1];
        const float wB0 = s_w2[2 * (off + j + 1) + 0];
        const float wB1 = s_w2[2 * (off + j + 1) + 1];
        #pragma unroll
        for (int el = 0; el < 4; el++) {
            float a, b;
            unpack2(h[el][q], a, b);
            const float tA = fast_tanh(a);
            const float tB = fast_tanh(b);
            p0[el] = fmaf(tA, wA0, p0[el]); p1[el] = fmaf(tA, wA1, p1[el]);
            p0[el] = fmaf(tB, wB0, p0[el]); p1[el] = fmaf(tB, wB1, p1[el]);
        }
    }
    // total for MY owned elements = my partial[0/1] + partner's partial[2/3].
    // shfl_xor(p[2]) swaps "partner-element" partials between the two lanes.
    const float q0A = p0[0] + __shfl_xor_sync(0xffffffffu, p0[2], 1);
    const float q1A = p1[0] + __shfl_xor_sync(0xffffffffu, p1[2], 1);
    const float q0B = p0[1] + __shfl_xor_sync(0xffffffffu, p0[3], 1);
    const float q1B = p1[1] + __shfl_xor_sync(0xffffffffu, p1[3], 1);

    // ---- fc1 + stores: each lane finishes its 2 owned elements ----
    {
        const float b20 = b2[0], b21 = b2[1];
        const float o0A = q0A + b20, o1A = q1A + b21;
        const float o0B = q0B + b20, o1B = q1B + b21;

        float o2A = fb2[0], o2B = o2A;
        #pragma unroll
        for (int m = 0; m < 4; m++) {
            const float w1a = fw1[m], w1b = fw1[4 + m], w2m = fw2[m], fbm = fb1[m];
            const float tA = fast_tanh(fbm + fmaf(o0A, w1a, o1A * w1b));
            const float tB = fast_tanh(fbm + fmaf(o0B, w1a, o1B * w1b));
            o2A = fmaf(tA, w2m, o2A);
            o2B = fmaf(tB, w2m, o2B);
        }
        out[3*eA+0] = o0A; out[3*eA+1] = o1A; out[3*eA+2] = o2A;
        out[3*eB+0] = o0B; out[3*eB+1] = o1B; out[3*eB+2] = o2B;
    }
}

} // anonymous namespace

extern "C" void kernel_launch(void* const* d_in, const int* in_sizes, int n_in,
                              void* d_out, int out_size) {
    const int*   vals = (const int*)  d_in[0];
    const float* dist = (const float*)d_in[1];
    const float* w1   = (const float*)d_in[2];
    const float* b1   = (const float*)d_in[3];
    const float* w2   = (const float*)d_in[4];
    const float* b2   = (const float*)d_in[5];
    const float* fw1  = (const float*)d_in[6];
    const float* fb1  = (const float*)d_in[7];
    const float* fw2  = (const float*)d_in[8];
    const float* fb2  = (const float*)d_in[9];
    float* out = (float*)d_out;

    const int n = in_sizes[0] / KNN;        // B*S elements (multiple of 4 here)
    const int total = n / 2;                // 2 lanes per 4 elements
    const int blocks = (total + TPB - 1) / TPB;
    meta_kernel<<<blocks, TPB>>>(vals, dist, w1, b1, w2, b2,
                                 fw1, fb1, fw2, fb2, out, n);
}

// round 16
// speedup vs baseline: 1.2113x; 1.2113x over previous
#include <cuda_runtime.h>
#include <cstdint>

namespace {

constexpr int KNN  = 32;   // K nearest neighbors
constexpr int IN2  = 64;   // 2K MLP input
constexpr int MID  = 32;   // hidden width of fc2
constexpr int HALF = 16;   // hidden units per lane (pair splits 32 cols)
constexpr int TPB  = 128;  // 4 warps/CTA -> one per SMSP (wid%4 mapping)

__device__ __forceinline__ float fast_tanh(float x) {
    float y;
    asm("tanh.approx.f32 %0, %1;" : "=f"(y) : "f"(x));
    return y;
}
__device__ __forceinline__ unsigned long long pack2(float x) {
    unsigned long long r;
    asm("mov.b64 %0, {%1, %1};" : "=l"(r) : "f"(x));
    return r;
}
__device__ __forceinline__ void ffma2(unsigned long long& d,
                                      unsigned long long a,
                                      unsigned long long b) {
    asm("fma.rn.f32x2 %0, %1, %2, %0;" : "+l"(d) : "l"(a), "l"(b));
}
__device__ __forceinline__ void unpack2(unsigned long long p, float& lo, float& hi) {
    asm("mov.b64 {%0, %1}, %2;" : "=f"(lo), "=f"(hi) : "l"(p));
}

// grid is 256 CTAs -> <=2 resident CTAs/SM; 65536/(128*2) = 256-reg budget.
__global__ __launch_bounds__(TPB, 2) void meta_kernel(
    const int*   __restrict__ vals,
    const float* __restrict__ dist,
    const float* __restrict__ w1,   // [64,32]
    const float* __restrict__ b1,   // [32]
    const float* __restrict__ w2,   // [32,2]
    const float* __restrict__ b2,   // [2]
    const float* __restrict__ fw1,  // [2,4]
    const float* __restrict__ fb1,  // [4]
    const float* __restrict__ fw2,  // [4,1]
    const float* __restrict__ fb2,  // [1]
    float* __restrict__ out,        // [n,3]
    int n)
{
    __shared__ __align__(16) float s_w1[IN2 * MID];
    __shared__ __align__(16) float s_b1[MID];
    __shared__ __align__(16) float s_w2[MID * 2];

    {
        const int tid = threadIdx.x;
        #pragma unroll
        for (int i = 0; i < (IN2 * MID) / TPB; i++) s_w1[tid + i * TPB] = w1[tid + i * TPB];
        if (tid < MID)     s_b1[tid] = b1[tid];
        if (tid < MID * 2) s_w2[tid] = w2[tid];
        __syncthreads();
    }

    const int gt   = blockIdx.x * TPB + threadIdx.x;
    const int pair = gt >> 1;          // lane pair index
    const int half = gt & 1;           // column half AND bitmap word owner
    const int e0   = 2 * pair;         // this thread pair handles elements e0,e1
    const int e1   = e0 + 1;
    if (e1 >= n) return;               // n is even for this problem
    const int off  = half * HALF;

    // ---- stage 1: label loads for both elements (16 LDG.128 in flight) ----
    int4 v0[KNN / 4], v1[KNN / 4];
    {
        const int4* vp0 = reinterpret_cast<const int4*>(vals + (size_t)e0 * KNN);
        const int4* vp1 = reinterpret_cast<const int4*>(vals + (size_t)e1 * KNN);
        #pragma unroll
        for (int c = 0; c < KNN / 4; c++) v0[c] = vp0[c];
        #pragma unroll
        for (int c = 0; c < KNN / 4; c++) v1[c] = vp1[c];
    }

    // ---- split bitmaps: even lane owns labels [0,64), odd lane [64,128) ----
    unsigned flags0 = 0u, flags1 = 0u;
    {
        const bool want_hi = (half == 1);
        uint64_t seen0 = want_hi ? 0ull : 1ull;   // bit0 preseed kills label 0
        uint64_t seen1 = seen0;
        #pragma unroll
        for (int c = 0; c < KNN / 4; c++) {
            const int4 a = v0[c];
            const int4 b = v1[c];
            const int va[4] = {a.x, a.y, a.z, a.w};
            const int vb[4] = {b.x, b.y, b.z, b.w};
            #pragma unroll
            for (int r = 0; r < 4; r++) {
                const int k = 4 * c + r;
                {
                    const int val = va[r];
                    const bool mine = ((val >= 64) == want_hi);
                    const uint64_t m = 1ull << (val & 63);
                    const bool isnew = mine && ((seen0 & m) == 0ull);
                    if (mine) seen0 |= m;
                    flags0 |= isnew ? (1u << k) : 0u;
                }
                {
                    const int val = vb[r];
                    const bool mine = ((val >= 64) == want_hi);
                    const uint64_t m = 1ull << (val & 63);
                    const bool isnew = mine && ((seen1 & m) == 0ull);
                    if (mine) seen1 |= m;
                    flags1 |= isnew ? (1u << k) : 0u;
                }
            }
        }
        flags0 |= __shfl_xor_sync(0xffffffffu, flags0, 1);
        flags1 |= __shfl_xor_sync(0xffffffffu, flags1, 1);
    }

    // ---- stage 2: distance loads (latency hides behind phase B) ----
    float4 d0[KNN / 4], d1[KNN / 4];
    {
        const float4* dp0 = reinterpret_cast<const float4*>(dist + (size_t)e0 * KNN);
        const float4* dp1 = reinterpret_cast<const float4*>(dist + (size_t)e1 * KNN);
        #pragma unroll
        for (int c = 0; c < KNN / 4; c++) d0[c] = dp0[c];
        #pragma unroll
        for (int c = 0; c < KNN / 4; c++) d1[c] = dp1[c];
    }

    // ---- init packed accumulators (both elements) with bias slice ----
    unsigned long long h0[HALF / 2], h1[HALF / 2];
    {
        const ulonglong2* bp = reinterpret_cast<const ulonglong2*>(s_b1 + off);
        #pragma unroll
        for (int q = 0; q < HALF / 4; q++) {
            ulonglong2 t = bp[q];
            h0[2*q+0] = t.x; h0[2*q+1] = t.y;
            h1[2*q+0] = t.x; h1[2*q+1] = t.y;
        }
    }

    // ---- phase B: label-count features; each weight load feeds BOTH elements ----
    #pragma unroll
    for (int k = 0; k < KNN; k++) {
        const unsigned long long cc0 = pack2((float)__popc(flags0 << (31 - k)));
        const unsigned long long cc1 = pack2((float)__popc(flags1 << (31 - k)));
        const ulonglong2* wr = reinterpret_cast<const ulonglong2*>(
            s_w1 + (KNN + k) * MID + off);
        #pragma unroll
        for (int q = 0; q < HALF / 4; q++) {
            ulonglong2 w = wr[q];
            ffma2(h0[2*q+0], cc0, w.x);
            ffma2(h0[2*q+1], cc0, w.y);
            ffma2(h1[2*q+0], cc1, w.x);
            ffma2(h1[2*q+1], cc1, w.y);
        }
    }

    // ---- phase A: distance features; shared weight loads again ----
    #pragma unroll
    for (int c = 0; c < KNN / 4; c++) {
        const float4 ta = d0[c];
        const float4 tb = d1[c];
        const float xa[4] = {ta.x, ta.y, ta.z, ta.w};
        const float xb[4] = {tb.x, tb.y, tb.z, tb.w};
        #pragma unroll
        for (int r = 0; r < 4; r++) {
            const unsigned long long xx0 = pack2(xa[r]);
            const unsigned long long xx1 = pack2(xb[r]);
            const ulonglong2* wr = reinterpret_cast<const ulonglong2*>(
                s_w1 + (4 * c + r) * MID + off);
            #pragma unroll
            for (int q = 0; q < HALF / 4; q++) {
                ulonglong2 w = wr[q];
                ffma2(h0[2*q+0], xx0, w.x);
                ffma2(h0[2*q+1], xx0, w.y);
                ffma2(h1[2*q+0], xx1, w.x);
                ffma2(h1[2*q+1], xx1, w.y);
            }
        }
    }

    // ---- fc2 layer 2: partials for both elements over this thread's 16 cols ----
    float p00 = 0.f, p01 = 0.f, p10 = 0.f, p11 = 0.f;
    #pragma unroll
    for (int q = 0; q < HALF / 2; q++) {
        const int j = 2 * q;
        const float w2a0 = s_w2[2 * (off + j) + 0];
        const float w2a1 = s_w2[2 * (off + j) + 1];
        const float w2b0 = s_w2[2 * (off + j + 1) + 0];
        const float w2b1 = s_w2[2 * (off + j + 1) + 1];
        float a, b;
        unpack2(h0[q], a, b);
        {
            const float tA = fast_tanh(a), tB = fast_tanh(b);
            p00 = fmaf(tA, w2a0, p00); p01 = fmaf(tA, w2a1, p01);
            p00 = fmaf(tB, w2b0, p00); p01 = fmaf(tB, w2b1, p01);
        }
        unpack2(h1[q], a, b);
        {
            const float tA = fast_tanh(a), tB = fast_tanh(b);
            p10 = fmaf(tA, w2a0, p10); p11 = fmaf(tA, w2a1, p11);
            p10 = fmaf(tB, w2b0, p10); p11 = fmaf(tB, w2b1, p11);
        }
    }
    p00 += __shfl_xor_sync(0xffffffffu, p00, 1);
    p01 += __shfl_xor_sync(0xffffffffu, p01, 1);
    p10 += __shfl_xor_sync(0xffffffffu, p10, 1);
    p11 += __shfl_xor_sync(0xffffffffu, p11, 1);

    // ---- fc1 + stores (even lane of the pair only) ----
    if (half == 0) {
        const float fbv[4] = {fb1[0], fb1[1], fb1[2], fb1[3]};
        const float b20 = b2[0], b21 = b2[1];

        const float o00 = p00 + b20, o01 = p01 + b21;
        const float o10 = p10 + b20, o11 = p11 + b21;

        float o02 = fb2[0], o12 = o02;
        #pragma unroll
        for (int m = 0; m < 4; m++) {
            const float w1a = fw1[m], w1b = fw1[4 + m], w2m = fw2[m];
            const float t0 = fast_tanh(fbv[m] + fmaf(o00, w1a, o01 * w1b));
            const float t1 = fast_tanh(fbv[m] + fmaf(o10, w1a, o11 * w1b));
            o02 = fmaf(t0, w2m, o02);
            o12 = fmaf(t1, w2m, o12);
        }
        out[3*e0+0] = o00; out[3*e0+1] = o01; out[3*e0+2] = o02;
        out[3*e1+0] = o10; out[3*e1+1] = o11; out[3*e1+2] = o12;
    }
}

} // anonymous namespace

extern "C" void kernel_launch(void* const* d_in, const int* in_sizes, int n_in,
                              void* d_out, int out_size) {
    const int*   vals = (const int*)  d_in[0];
    const float* dist = (const float*)d_in[1];
    const float* w1   = (const float*)d_in[2];
    const float* b1   = (const float*)d_in[3];
    const float* w2   = (const float*)d_in[4];
    const float* b2   = (const float*)d_in[5];
    const float* fw1  = (const float*)d_in[6];
    const float* fb1  = (const float*)d_in[7];
    const float* fw2  = (const float*)d_in[8];
    const float* fb2  = (const float*)d_in[9];
    float* out = (float*)d_out;

    const int n = in_sizes[0] / KNN;        // B*S elements (even)
    const int total = n;                    // 2 lanes per 2 elements -> n threads
    const int blocks = (total + TPB - 1) / TPB;
    meta_kernel<<<blocks, TPB>>>(vals, dist, w1, b1, w2, b2,
                                 fw1, fb1, fw2, fb2, out, n);
}